// round 1
// baseline (speedup 1.0000x reference)
#include <cuda_runtime.h>
#include <stdint.h>

// RadarDopSparseProcessor — exact 0.9-quantile threshold + ordered compaction.
// B=4 batches, N=40*320*320=4,096,000 voxels each.
// thr = exact order statistic at rank floor(0.9f*(N-1)) = 3686399 (frac==0 in f32).

#define Bn 4
#define Zd 40
#define Yd 320
#define Xd 320
#define Nv (Zd*Yd*Xd)            // 4,096,000
#define Kpad (Nv/10 + 64)        // 409,664
#define BKr (Bn*Kpad)            // 1,638,656

#define H1_BINS 4096             // top 12 bits of float pattern
#define H2_BINS 4096             // next 12 bits
#define H3_BINS 256              // last 8 bits

#define CH_BLOCKS 80
#define CH_ELEMS (Nv/CH_BLOCKS)  // 51,200
#define CT_BLOCKS 1000
#define CT_ELEMS (Nv/CT_BLOCKS)  // 4,096

__device__ unsigned g_hist1[Bn][H1_BINS];
__device__ unsigned g_hist2[Bn][2][H2_BINS];
__device__ unsigned g_hist3[Bn][2][H3_BINS];
__device__ unsigned g_sel1[Bn][2];
__device__ unsigned g_rem1[Bn][2];
__device__ unsigned g_sel2[Bn][2];   // 24-bit prefix
__device__ unsigned g_rem2[Bn][2];
__device__ float    g_thr[Bn];
__device__ unsigned g_blockcnt[Bn][CT_BLOCKS];
__device__ unsigned g_blockoff[Bn][CT_BLOCKS];

__device__ __forceinline__ unsigned warp_iscan(unsigned v){
  #pragma unroll
  for (int d=1; d<32; d<<=1){
    unsigned n = __shfl_up_sync(0xFFFFFFFFu, v, d);
    if ((threadIdx.x & 31) >= d) v += n;
  }
  return v;
}

__global__ __launch_bounds__(256) void k_zero(){
  int i = blockIdx.x*blockDim.x + threadIdx.x;
  if (i < Bn*H1_BINS)    (&g_hist1[0][0])[i]    = 0u;
  if (i < Bn*2*H2_BINS)  (&g_hist2[0][0][0])[i] = 0u;
  if (i < Bn*2*H3_BINS)  (&g_hist3[0][0][0])[i] = 0u;
}

// ---------------- pass 1: 12-bit histogram (bits 31..20) ----------------
__global__ __launch_bounds__(512) void k_hist1(const float* __restrict__ cube){
  __shared__ unsigned hist[H1_BINS];
  int b = blockIdx.y;
  const float4* p = (const float4*)(cube + (size_t)b*Nv + (size_t)blockIdx.x*CH_ELEMS);
  for (int i=threadIdx.x;i<H1_BINS;i+=512) hist[i]=0u;
  __syncthreads();
  const int nvec = CH_ELEMS/4;
  for (int i=threadIdx.x;i<nvec;i+=512){
    float4 v = p[i];
    atomicAdd(&hist[__float_as_uint(v.x)>>20],1u);
    atomicAdd(&hist[__float_as_uint(v.y)>>20],1u);
    atomicAdd(&hist[__float_as_uint(v.z)>>20],1u);
    atomicAdd(&hist[__float_as_uint(v.w)>>20],1u);
  }
  __syncthreads();
  for (int i=threadIdx.x;i<H1_BINS;i+=512){
    unsigned c=hist[i];
    if (c) atomicAdd(&g_hist1[b][i], c);
  }
}

__global__ __launch_bounds__(1024) void k_select1(){
  int b = blockIdx.x; int tid = threadIdx.x;
  __shared__ unsigned s[H1_BINS];
  __shared__ unsigned wq[32];
  for (int i=tid;i<H1_BINS;i+=1024) s[i]=g_hist1[b][i];
  __syncthreads();
  unsigned l0=s[tid*4+0],l1=s[tid*4+1],l2=s[tid*4+2],l3=s[tid*4+3];
  unsigned sum=l0+l1+l2+l3;
  unsigned inc=warp_iscan(sum);
  if((tid&31)==31) wq[tid>>5]=inc;
  __syncthreads();
  if(tid==0){unsigned run=0; for(int k=0;k<32;k++){unsigned t=wq[k];wq[k]=run;run+=t;}}
  __syncthreads();
  unsigned excl = inc - sum + wq[tid>>5];
  const float pos = 0.9f * (float)(Nv-1);        // == 3686399.0f exactly
  unsigned r0 = (unsigned)floorf(pos);
  unsigned r1 = (unsigned)ceilf(pos); if (r1 > Nv-1) r1 = Nv-1;
  unsigned ranks[2] = {r0, r1};
  for (int j=0;j<2;j++){
    unsigned r = ranks[j];
    if (r>=excl && r<excl+sum){
      unsigned c=excl; unsigned loc[4]={l0,l1,l2,l3};
      #pragma unroll
      for(int k2=0;k2<4;k2++){
        if (r < c+loc[k2]){ g_sel1[b][j]=(unsigned)(tid*4+k2); g_rem1[b][j]=r-c; break; }
        c+=loc[k2];
      }
    }
  }
}

// ---------------- pass 2: 12-bit histogram (bits 19..8), restricted ----------------
__global__ __launch_bounds__(512) void k_hist2(const float* __restrict__ cube){
  __shared__ unsigned hist[2][H2_BINS];
  int b=blockIdx.y;
  unsigned sA=g_sel1[b][0], sB=g_sel1[b][1];
  for (int i=threadIdx.x;i<2*H2_BINS;i+=512) (&hist[0][0])[i]=0u;
  __syncthreads();
  const float4* p=(const float4*)(cube + (size_t)b*Nv + (size_t)blockIdx.x*CH_ELEMS);
  const int nvec=CH_ELEMS/4;
  for (int i=threadIdx.x;i<nvec;i+=512){
    float4 v=p[i]; unsigned u;
    u=__float_as_uint(v.x); if((u>>20)==sA) atomicAdd(&hist[0][(u>>8)&0xFFFu],1u); else if((u>>20)==sB) atomicAdd(&hist[1][(u>>8)&0xFFFu],1u);
    u=__float_as_uint(v.y); if((u>>20)==sA) atomicAdd(&hist[0][(u>>8)&0xFFFu],1u); else if((u>>20)==sB) atomicAdd(&hist[1][(u>>8)&0xFFFu],1u);
    u=__float_as_uint(v.z); if((u>>20)==sA) atomicAdd(&hist[0][(u>>8)&0xFFFu],1u); else if((u>>20)==sB) atomicAdd(&hist[1][(u>>8)&0xFFFu],1u);
    u=__float_as_uint(v.w); if((u>>20)==sA) atomicAdd(&hist[0][(u>>8)&0xFFFu],1u); else if((u>>20)==sB) atomicAdd(&hist[1][(u>>8)&0xFFFu],1u);
  }
  __syncthreads();
  for (int i=threadIdx.x;i<2*H2_BINS;i+=512){
    unsigned c=(&hist[0][0])[i];
    if (c) atomicAdd((&g_hist2[b][0][0])+i, c);
  }
}

__global__ __launch_bounds__(1024) void k_select2(){
  int b=blockIdx.x; int tid=threadIdx.x;
  __shared__ unsigned s[H2_BINS];
  __shared__ unsigned wq[32];
  unsigned sA=g_sel1[b][0], sB=g_sel1[b][1];
  bool same = (sA==sB);
  int np = same?1:2;
  for (int p=0;p<np;p++){
    for (int i=tid;i<H2_BINS;i+=1024) s[i]=g_hist2[b][p][i];
    __syncthreads();
    unsigned l0=s[tid*4+0],l1=s[tid*4+1],l2=s[tid*4+2],l3=s[tid*4+3];
    unsigned sum=l0+l1+l2+l3;
    unsigned inc=warp_iscan(sum);
    if((tid&31)==31) wq[tid>>5]=inc;
    __syncthreads();
    if(tid==0){unsigned run=0; for(int k=0;k<32;k++){unsigned t=wq[k];wq[k]=run;run+=t;}}
    __syncthreads();
    unsigned excl = inc - sum + wq[tid>>5];
    for (int j=0;j<2;j++){
      bool act = same ? (p==0) : (j==p);
      if (act){
        unsigned r=g_rem1[b][j];
        if (r>=excl && r<excl+sum){
          unsigned c=excl; unsigned loc[4]={l0,l1,l2,l3};
          #pragma unroll
          for(int k2=0;k2<4;k2++){
            if (r < c+loc[k2]){ g_sel2[b][j]=(g_sel1[b][j]<<12)|(unsigned)(tid*4+k2); g_rem2[b][j]=r-c; break; }
            c+=loc[k2];
          }
        }
      }
    }
    __syncthreads();
  }
}

// ---------------- pass 3: 8-bit histogram (bits 7..0), restricted ----------------
__global__ __launch_bounds__(512) void k_hist3(const float* __restrict__ cube){
  int b=blockIdx.y;
  unsigned p0=g_sel2[b][0], p1=g_sel2[b][1];
  const float4* p=(const float4*)(cube + (size_t)b*Nv + (size_t)blockIdx.x*CH_ELEMS);
  const int nvec=CH_ELEMS/4;
  for (int i=threadIdx.x;i<nvec;i+=512){
    float4 v=p[i]; unsigned u, pre;
    u=__float_as_uint(v.x); pre=u>>8; if(pre==p0) atomicAdd(&g_hist3[b][0][u&0xFFu],1u); else if(pre==p1) atomicAdd(&g_hist3[b][1][u&0xFFu],1u);
    u=__float_as_uint(v.y); pre=u>>8; if(pre==p0) atomicAdd(&g_hist3[b][0][u&0xFFu],1u); else if(pre==p1) atomicAdd(&g_hist3[b][1][u&0xFFu],1u);
    u=__float_as_uint(v.z); pre=u>>8; if(pre==p0) atomicAdd(&g_hist3[b][0][u&0xFFu],1u); else if(pre==p1) atomicAdd(&g_hist3[b][1][u&0xFFu],1u);
    u=__float_as_uint(v.w); pre=u>>8; if(pre==p0) atomicAdd(&g_hist3[b][0][u&0xFFu],1u); else if(pre==p1) atomicAdd(&g_hist3[b][1][u&0xFFu],1u);
  }
}

__global__ __launch_bounds__(256) void k_select3(){
  int b=blockIdx.x; int tid=threadIdx.x;
  __shared__ unsigned s[H3_BINS];
  __shared__ unsigned wq[8];
  __shared__ float vres[2];
  unsigned p0=g_sel2[b][0], p1=g_sel2[b][1];
  bool same = (p0==p1);
  int np = same?1:2;
  for (int p=0;p<np;p++){
    s[tid]=g_hist3[b][p][tid];
    __syncthreads();
    unsigned v=s[tid];
    unsigned inc=warp_iscan(v);
    if((tid&31)==31) wq[tid>>5]=inc;
    __syncthreads();
    if(tid==0){unsigned run=0; for(int k=0;k<8;k++){unsigned t=wq[k];wq[k]=run;run+=t;}}
    __syncthreads();
    unsigned excl = inc - v + wq[tid>>5];
    for (int j=0;j<2;j++){
      bool act = same ? (p==0) : (j==p);
      if (act){
        unsigned r = g_rem2[b][j];
        if (r>=excl && r<excl+v){
          vres[j]=__uint_as_float((g_sel2[b][j]<<8)|(unsigned)tid);
        }
      }
    }
    __syncthreads();
  }
  if (tid==0){
    const float pos = 0.9f * (float)(Nv-1);
    float frac = pos - floorf(pos);            // == 0.0f for this shape
    float v0 = vres[0];
    float v1 = vres[1];
    g_thr[b] = v0*(1.0f-frac) + v1*frac;       // jnp 'linear' interpolation
  }
}

// ---------------- compaction ----------------
__global__ __launch_bounds__(512) void k_count(const float* __restrict__ cube){
  __shared__ unsigned ws[16];
  int b=blockIdx.y; float thr=g_thr[b];
  const float4* p=(const float4*)(cube + (size_t)b*Nv + (size_t)blockIdx.x*CT_ELEMS + (size_t)threadIdx.x*8);
  float4 a=p[0], c=p[1];
  unsigned cnt = (a.x>thr)+(a.y>thr)+(a.z>thr)+(a.w>thr)
               + (c.x>thr)+(c.y>thr)+(c.z>thr)+(c.w>thr);
  #pragma unroll
  for (int d=16;d>0;d>>=1) cnt += __shfl_down_sync(0xFFFFFFFFu,cnt,d);
  if ((threadIdx.x&31)==0) ws[threadIdx.x>>5]=cnt;
  __syncthreads();
  if (threadIdx.x==0){
    unsigned t=0; for(int k=0;k<16;k++) t+=ws[k];
    g_blockcnt[b][blockIdx.x]=t;
  }
}

__global__ __launch_bounds__(1024) void k_scan(){
  __shared__ unsigned wq[32];
  int b=blockIdx.x; int tid=threadIdx.x;
  unsigned v = (tid<CT_BLOCKS)? g_blockcnt[b][tid] : 0u;
  unsigned inc=warp_iscan(v);
  if((tid&31)==31) wq[tid>>5]=inc;
  __syncthreads();
  if(tid==0){unsigned run=0; for(int k=0;k<32;k++){unsigned t=wq[k];wq[k]=run;run+=t;}}
  __syncthreads();
  unsigned excl=inc-v+wq[tid>>5];
  if (tid<CT_BLOCKS) g_blockoff[b][tid]=excl;
}

__global__ __launch_bounds__(512) void k_scatter(const float* __restrict__ cube,
                                                const float* __restrict__ dop,
                                                float* __restrict__ out, int out_elems){
  __shared__ unsigned wq[16];
  int b=blockIdx.y; float thr=g_thr[b];
  size_t sbase = (size_t)b*Nv + (size_t)blockIdx.x*CT_ELEMS;
  int tid=threadIdx.x;
  const float4* p=(const float4*)(cube + sbase + (size_t)tid*8);
  float4 a=p[0], c=p[1];
  float v[8]={a.x,a.y,a.z,a.w,c.x,c.y,c.z,c.w};
  unsigned cnt=0;
  #pragma unroll
  for (int k=0;k<8;k++) cnt += (v[k]>thr) ? 1u : 0u;
  unsigned inc=warp_iscan(cnt);
  if((tid&31)==31) wq[tid>>5]=inc;
  __syncthreads();
  if(tid==0){unsigned run=0; for(int k=0;k<16;k++){unsigned t=wq[k];wq[k]=run;run+=t;}}
  __syncthreads();
  unsigned o = g_blockoff[b][blockIdx.x] + inc - cnt + wq[tid>>5];
  unsigned lbase = (unsigned)blockIdx.x*CT_ELEMS + (unsigned)tid*8;
  #pragma unroll
  for (int k=0;k<8;k++){
    if (v[k]>thr){
      unsigned gidx = lbase + (unsigned)k;
      unsigned z = gidx/(Yd*Xd);
      unsigned rem = gidx - z*(Yd*Xd);
      unsigned y = rem/Xd;
      unsigned x = rem - y*Xd;
      unsigned row = (unsigned)b*Kpad + o;
      float dv = dop[(size_t)b*Nv + gidx];
      size_t f = (size_t)row*5;
      if (f + 5 <= (size_t)out_elems){
        out[f+0] = ((float)x/320.0f)*72.0f;
        out[f+1] = ((float)y/320.0f)*32.0f;
        out[f+2] = ((float)z/40.0f)*8.0f;
        out[f+3] = v[k] / 10000000000000.0f;
        out[f+4] = dv - 1.9326f;
      }
      size_t ioff = (size_t)BKr*5 + (size_t)row*4;
      if (ioff + 4 <= (size_t)out_elems){
        out[ioff+0]=(float)b; out[ioff+1]=(float)z;
        out[ioff+2]=(float)y; out[ioff+3]=(float)x;
      }
      size_t voff = (size_t)BKr*9 + (size_t)row;
      if (voff < (size_t)out_elems) out[voff] = 1.0f;
      o++;
    }
  }
}

extern "C" void kernel_launch(void* const* d_in, const int* in_sizes, int n_in,
                              void* d_out, int out_size) {
  const float* cube = (const float*)d_in[0];
  const float* dop  = (const float*)d_in[1];
  float* out = (float*)d_out;

  cudaMemsetAsync(d_out, 0, (size_t)out_size * sizeof(float));
  k_zero<<<128,256>>>();

  dim3 gh(CH_BLOCKS, Bn);
  k_hist1<<<gh,512>>>(cube);
  k_select1<<<Bn,1024>>>();
  k_hist2<<<gh,512>>>(cube);
  k_select2<<<Bn,1024>>>();
  k_hist3<<<gh,512>>>(cube);
  k_select3<<<Bn,256>>>();

  dim3 gc(CT_BLOCKS, Bn);
  k_count<<<gc,512>>>(cube);
  k_scan<<<Bn,1024>>>();
  k_scatter<<<gc,512>>>(cube, dop, out, out_size);
}